// round 1
// baseline (speedup 1.0000x reference)
#include <cuda_runtime.h>

#define C_DIM 512
#define NSP   4096            // 64*64 spatial tokens
#define BATCH 2
#define NGROUPS 32
#define GCH   (C_DIM / NGROUPS)   // 16 channels per group

// ---------------- scratch (static device globals: allowed) ----------------
__device__ float g_hn[(size_t)BATCH * C_DIM * NSP];   // groupnorm output
__device__ float g_q [(size_t)BATCH * C_DIM * NSP];
__device__ float g_k [(size_t)BATCH * C_DIM * NSP];
__device__ float g_v [(size_t)BATCH * C_DIM * NSP];
__device__ float g_ao[(size_t)BATCH * C_DIM * NSP];   // attention output (pre-proj)
__device__ float g_sc[(size_t)BATCH * NSP * NSP];     // scores / attn (in-place softmax)

// ---------------- block reductions ----------------
__device__ __forceinline__ float block_sum(float v) {
    __shared__ float sm[32];
    int w = threadIdx.x >> 5, l = threadIdx.x & 31;
    #pragma unroll
    for (int o = 16; o; o >>= 1) v += __shfl_xor_sync(0xffffffffu, v, o);
    __syncthreads();
    if (l == 0) sm[w] = v;
    __syncthreads();
    if (w == 0) {
        v = (l < (int)(blockDim.x >> 5)) ? sm[l] : 0.f;
        #pragma unroll
        for (int o = 16; o; o >>= 1) v += __shfl_xor_sync(0xffffffffu, v, o);
        if (l == 0) sm[0] = v;
    }
    __syncthreads();
    return sm[0];
}

__device__ __forceinline__ float block_max(float v) {
    __shared__ float sm[32];
    int w = threadIdx.x >> 5, l = threadIdx.x & 31;
    #pragma unroll
    for (int o = 16; o; o >>= 1) v = fmaxf(v, __shfl_xor_sync(0xffffffffu, v, o));
    __syncthreads();
    if (l == 0) sm[w] = v;
    __syncthreads();
    if (w == 0) {
        v = (l < (int)(blockDim.x >> 5)) ? sm[l] : -INFINITY;
        #pragma unroll
        for (int o = 16; o; o >>= 1) v = fmaxf(v, __shfl_xor_sync(0xffffffffu, v, o));
        if (l == 0) sm[0] = v;
    }
    __syncthreads();
    return sm[0];
}

// ---------------- GroupNorm ----------------
// grid: 64 blocks = BATCH * NGROUPS, 256 threads. Group = 16 ch * 4096 = 65536 elems.
__global__ void __launch_bounds__(256)
groupnorm_kernel(const float* __restrict__ x, const float* __restrict__ gamma,
                 const float* __restrict__ beta, float* __restrict__ hn) {
    int b = blockIdx.x >> 5;
    int g = blockIdx.x & 31;
    const size_t base = ((size_t)b * C_DIM + (size_t)g * GCH) * NSP;
    const float4* xp = (const float4*)(x + base);
    float4* hp = (float4*)(hn + base);
    const int NV = GCH * NSP / 4;   // 16384 float4

    float s = 0.f, s2 = 0.f;
    for (int i = threadIdx.x; i < NV; i += 256) {
        float4 v = xp[i];
        s  += v.x + v.y + v.z + v.w;
        s2 += v.x * v.x + v.y * v.y + v.z * v.z + v.w * v.w;
    }
    float ts  = block_sum(s);
    float ts2 = block_sum(s2);
    const float invn = 1.f / (GCH * NSP);
    float mean = ts * invn;
    float var  = ts2 * invn - mean * mean;
    float inv  = rsqrtf(var + 1e-6f);

    for (int i = threadIdx.x; i < NV; i += 256) {
        int c = g * GCH + (i >> 10);          // 1024 float4 per channel row
        float gm = gamma[c] * inv;
        float bt = beta[c] - mean * gm;
        float4 v = xp[i];
        v.x = v.x * gm + bt; v.y = v.y * gm + bt;
        v.z = v.z * gm + bt; v.w = v.w * gm + bt;
        hp[i] = v;
    }
}

// ---------------- generic strided SGEMM ----------------
// C[m,n] = alpha * sum_k A(m,k)*B(k,n) + bias[m] (+ residual[m,n])
// A(m,k) at A[m*a_rs + k*a_cs]; B(k,n) at B[k*b_rs + n*b_cs]; C row stride c_rs, col stride 1.
// All dims multiples of 64 (M,N) and 16 (K). 256 threads, 64x64 tile, 4x4 microtile.
__global__ void __launch_bounds__(256)
sgemm_kernel(const float* __restrict__ A, const float* __restrict__ B,
             float* __restrict__ Cc, int K,
             int a_rs, int a_cs, int b_rs, int b_cs, int c_rs,
             float alpha, const float* __restrict__ bias,
             const float* __restrict__ residual) {
    __shared__ float As[16][68];
    __shared__ float Bs[16][68];

    const int tid = threadIdx.x;
    const int m0 = blockIdx.y * 64, n0 = blockIdx.x * 64;
    const int tr = (tid >> 4) << 2;   // 0..60
    const int tc = (tid & 15) << 2;   // 0..60
    const bool aK = (a_cs == 1);      // contiguous along k?
    const bool bK = (b_rs == 1);

    const float* Ab = A + (size_t)m0 * a_rs;
    const float* Bb = B + (size_t)n0 * b_cs;

    float acc[4][4] = {};

    for (int k0 = 0; k0 < K; k0 += 16) {
        #pragma unroll
        for (int i = 0; i < 4; i++) {
            int idx = tid + (i << 8);
            int m, ka;
            if (aK) { ka = idx & 15; m = idx >> 4; }
            else    { m  = idx & 63; ka = idx >> 6; }
            As[ka][m] = Ab[(size_t)m * a_rs + (size_t)(k0 + ka) * a_cs];
            int n, kb;
            if (bK) { kb = idx & 15; n = idx >> 4; }
            else    { n  = idx & 63; kb = idx >> 6; }
            Bs[kb][n] = Bb[(size_t)(k0 + kb) * b_rs + (size_t)n * b_cs];
        }
        __syncthreads();
        #pragma unroll
        for (int kk = 0; kk < 16; kk++) {
            float4 av = *(const float4*)&As[kk][tr];
            float4 bv = *(const float4*)&Bs[kk][tc];
            acc[0][0] += av.x * bv.x; acc[0][1] += av.x * bv.y;
            acc[0][2] += av.x * bv.z; acc[0][3] += av.x * bv.w;
            acc[1][0] += av.y * bv.x; acc[1][1] += av.y * bv.y;
            acc[1][2] += av.y * bv.z; acc[1][3] += av.y * bv.w;
            acc[2][0] += av.z * bv.x; acc[2][1] += av.z * bv.y;
            acc[2][2] += av.z * bv.z; acc[2][3] += av.z * bv.w;
            acc[3][0] += av.w * bv.x; acc[3][1] += av.w * bv.y;
            acc[3][2] += av.w * bv.z; acc[3][3] += av.w * bv.w;
        }
        __syncthreads();
    }

    #pragma unroll
    for (int i = 0; i < 4; i++) {
        int m = m0 + tr + i;
        float bb = bias ? bias[m] : 0.f;
        size_t off = (size_t)m * c_rs + (size_t)(n0 + tc);
        float4 vv;
        vv.x = acc[i][0] * alpha + bb;
        vv.y = acc[i][1] * alpha + bb;
        vv.z = acc[i][2] * alpha + bb;
        vv.w = acc[i][3] * alpha + bb;
        if (residual) {
            float4 r = *(const float4*)&residual[off];
            vv.x += r.x; vv.y += r.y; vv.z += r.z; vv.w += r.w;
        }
        *(float4*)&Cc[off] = vv;
    }
}

// ---------------- row softmax over 4096 (in place) ----------------
__global__ void __launch_bounds__(256)
softmax_kernel(float* __restrict__ sc) {
    float4* p = (float4*)(sc + (size_t)blockIdx.x * NSP);
    const int NV = NSP / 4;   // 1024

    float mx = -INFINITY;
    for (int i = threadIdx.x; i < NV; i += 256) {
        float4 v = p[i];
        mx = fmaxf(mx, fmaxf(fmaxf(v.x, v.y), fmaxf(v.z, v.w)));
    }
    mx = block_max(mx);

    float s = 0.f;
    for (int i = threadIdx.x; i < NV; i += 256) {
        float4 v = p[i];
        v.x = __expf(v.x - mx); v.y = __expf(v.y - mx);
        v.z = __expf(v.z - mx); v.w = __expf(v.w - mx);
        s += v.x + v.y + v.z + v.w;
        p[i] = v;
    }
    s = block_sum(s);
    float r = 1.f / s;
    for (int i = threadIdx.x; i < NV; i += 256) {
        float4 v = p[i];
        v.x *= r; v.y *= r; v.z *= r; v.w *= r;
        p[i] = v;
    }
}

// ---------------- launch ----------------
extern "C" void kernel_launch(void* const* d_in, const int* in_sizes, int n_in,
                              void* d_out, int out_size) {
    const float* x     = (const float*)d_in[0];
    const float* gamma = (const float*)d_in[1];
    const float* beta  = (const float*)d_in[2];
    const float* wq = (const float*)d_in[3];  const float* bq = (const float*)d_in[4];
    const float* wk = (const float*)d_in[5];  const float* bk = (const float*)d_in[6];
    const float* wv = (const float*)d_in[7];  const float* bv = (const float*)d_in[8];
    const float* wo = (const float*)d_in[9];  const float* bo = (const float*)d_in[10];
    float* out = (float*)d_out;

    float *hn, *q, *k, *v, *ao, *sc;
    cudaGetSymbolAddress((void**)&hn, g_hn);
    cudaGetSymbolAddress((void**)&q,  g_q);
    cudaGetSymbolAddress((void**)&k,  g_k);
    cudaGetSymbolAddress((void**)&v,  g_v);
    cudaGetSymbolAddress((void**)&ao, g_ao);
    cudaGetSymbolAddress((void**)&sc, g_sc);

    const size_t BO = (size_t)C_DIM * NSP;          // per-batch channel-plane
    const size_t SO = (size_t)NSP * NSP;            // per-batch score plane
    const float scale = 0.044194173824159216f;      // 512^-0.5

    groupnorm_kernel<<<BATCH * NGROUPS, 256>>>(x, gamma, beta, hn);

    // QKV: (512x512) @ (512x4096), A row-major (k contig), B row-major over [c][n]
    dim3 gw(NSP / 64, C_DIM / 64);
    for (int b = 0; b < BATCH; b++) {
        const float* hb = hn + b * BO;
        sgemm_kernel<<<gw, 256>>>(wq, hb, q + b * BO, C_DIM,
                                  C_DIM, 1, NSP, 1, NSP, 1.f, bq, nullptr);
        sgemm_kernel<<<gw, 256>>>(wk, hb, k + b * BO, C_DIM,
                                  C_DIM, 1, NSP, 1, NSP, 1.f, bk, nullptr);
        sgemm_kernel<<<gw, 256>>>(wv, hb, v + b * BO, C_DIM,
                                  C_DIM, 1, NSP, 1, NSP, 1.f, bv, nullptr);
    }

    // scores[b,i,j] = scale * sum_c q[b,c,i] k[b,c,j]
    // A(m=i,k=c): a_rs=1, a_cs=4096 ; B(k=c,n=j): b_rs=4096, b_cs=1
    dim3 gs(NSP / 64, NSP / 64);
    for (int b = 0; b < BATCH; b++) {
        sgemm_kernel<<<gs, 256>>>(q + b * BO, k + b * BO, sc + b * SO, C_DIM,
                                  1, NSP, NSP, 1, NSP, scale, nullptr, nullptr);
    }

    softmax_kernel<<<BATCH * NSP, 256>>>(sc);

    // out[b,c,i] = sum_j v[b,c,j] * attn[b,i,j]
    // A(m=c,k=j): a_rs=4096, a_cs=1 ; B(k=j,n=i)=attn[i][j]: b_rs=1, b_cs=4096
    dim3 go(NSP / 64, C_DIM / 64);
    for (int b = 0; b < BATCH; b++) {
        sgemm_kernel<<<go, 256>>>(v + b * BO, sc + b * SO, ao + b * BO, NSP,
                                  NSP, 1, 1, NSP, NSP, 1.f, nullptr, nullptr);
    }

    // proj + bias + residual: out = wo @ ao + bo + x
    for (int b = 0; b < BATCH; b++) {
        sgemm_kernel<<<gw, 256>>>(wo, ao + b * BO, out + b * BO, C_DIM,
                                  C_DIM, 1, NSP, 1, NSP, 1.f, bo, x + b * BO);
    }
}

// round 4
// speedup vs baseline: 3.7798x; 3.7798x over previous
#include <cuda_runtime.h>
#include <cstdint>
#include <cstddef>

#define C_DIM 512
#define NSP   4096
#define BATCH 2
#define NGROUPS 32
#define GCH 16

#define MT 128
#define NT 128
#define KC 32
#define KPAD 36                      // 32 + 4 words padding (bank-safe)
#define STAGE_WORDS (MT * KPAD)      // per A or B tile: 4608 words
#define SMEM_DYN (2 * 2 * STAGE_WORDS * 4)   // 73728 B

// ---------------- scratch ----------------
__device__ float g_hnT[(size_t)BATCH*NSP*C_DIM];   // [b][token][cin]
__device__ float g_q  [(size_t)BATCH*NSP*C_DIM];   // [b][token][cout]
__device__ float g_k  [(size_t)BATCH*NSP*C_DIM];
__device__ float g_v  [(size_t)BATCH*C_DIM*NSP];   // [b][cout][token]
__device__ float g_ao [(size_t)BATCH*NSP*C_DIM];   // [b][token][c]
__device__ float g_sc [(size_t)BATCH*NSP*NSP];     // [b][i][j]
__device__ float g_mean[BATCH*NGROUPS];
__device__ float g_inv [BATCH*NGROUPS];

__device__ __forceinline__ uint32_t f2tf32(float x) {
    uint32_t r; asm("cvt.rna.tf32.f32 %0, %1;" : "=r"(r) : "f"(x)); return r;
}

__device__ __forceinline__ void mma_tf32(float* d, const uint32_t* a, const uint32_t* b) {
    asm volatile(
        "mma.sync.aligned.m16n8k8.row.col.f32.tf32.tf32.f32 "
        "{%0,%1,%2,%3}, {%4,%5,%6,%7}, {%8,%9}, {%0,%1,%2,%3};"
        : "+f"(d[0]), "+f"(d[1]), "+f"(d[2]), "+f"(d[3])
        : "r"(a[0]), "r"(a[1]), "r"(a[2]), "r"(a[3]), "r"(b[0]), "r"(b[1]));
}

// ---------------- tf32 tensor-core GEMM ----------------
// D[m,n] = alpha * sum_k A[m,k]*B[n,k]   (A, B K-major, k contiguous)
// trans==0: C[m*ldc+n] = D + bias[n]
// trans==1: C[n*ldc+m] = D + bias[n] + resid[n*ldc+m]
__global__ void __launch_bounds__(256)
mma_gemm(const float* __restrict__ A, size_t aBat, int lda,
         const float* __restrict__ B, size_t bBat, int ldb,
         float* __restrict__ C, size_t cBat, int ldc,
         int K, float alpha,
         const float* __restrict__ bias,
         const float* __restrict__ resid, size_t rBat, int trans) {
    extern __shared__ uint32_t sm[];
    // stage s: A at s*2*STAGE_WORDS, B at s*2*STAGE_WORDS + STAGE_WORDS

    const int tid  = threadIdx.x;
    const int wid  = tid >> 5, lane = tid & 31;
    const int wm   = wid & 1;         // m-half (64)
    const int wn   = wid >> 1;        // n-quarter (32)
    const int g    = lane >> 2;       // 0..7
    const int t    = lane & 3;        // 0..3

    const int m0 = blockIdx.y * MT, n0 = blockIdx.x * NT;
    const int z  = blockIdx.z;
    A += z * aBat + (size_t)m0 * lda;
    B += z * bBat + (size_t)n0 * ldb;
    C += z * cBat;
    if (resid) resid += z * rBat;

    // per-thread global/smem tile coordinates (for the 4 float4 of A and of B)
    const int row = tid >> 3;          // 0..31, +32 per i
    const int kq4 = (tid & 7) << 2;    // 0,4,...,28

    float acc[4][4][4] = {};           // [mi][ni][reg]
    const int nch = K / KC;

    float4 ra[4], rb[4];
    // prologue: load + store chunk 0
    #pragma unroll
    for (int i = 0; i < 4; i++) {
        ra[i] = *(const float4*)(A + (size_t)(row + i * 32) * lda + kq4);
        rb[i] = *(const float4*)(B + (size_t)(row + i * 32) * ldb + kq4);
    }
    #pragma unroll
    for (int i = 0; i < 4; i++) {
        uint32_t* pa = sm + (row + i * 32) * KPAD + kq4;
        uint32_t* pb = pa + STAGE_WORDS;
        uint4 ua = { f2tf32(ra[i].x), f2tf32(ra[i].y), f2tf32(ra[i].z), f2tf32(ra[i].w) };
        uint4 ub = { f2tf32(rb[i].x), f2tf32(rb[i].y), f2tf32(rb[i].z), f2tf32(rb[i].w) };
        *(uint4*)pa = ua;
        *(uint4*)pb = ub;
    }
    __syncthreads();

    for (int c = 0; c < nch; c++) {
        const int st = c & 1;
        const bool more = (c + 1 < nch);
        if (more) {
            const int kc = (c + 1) * KC;
            #pragma unroll
            for (int i = 0; i < 4; i++) {
                ra[i] = *(const float4*)(A + (size_t)(row + i * 32) * lda + kc + kq4);
                rb[i] = *(const float4*)(B + (size_t)(row + i * 32) * ldb + kc + kq4);
            }
        }
        const uint32_t* As = sm + st * 2 * STAGE_WORDS;
        const uint32_t* Bs = As + STAGE_WORDS;
        #pragma unroll
        for (int ks = 0; ks < 4; ks++) {
            const int kk = ks * 8 + t;
            uint32_t af[4][4];
            #pragma unroll
            for (int mi = 0; mi < 4; mi++) {
                int m = wm * 64 + mi * 16 + g;
                af[mi][0] = As[m * KPAD + kk];
                af[mi][1] = As[(m + 8) * KPAD + kk];
                af[mi][2] = As[m * KPAD + kk + 4];
                af[mi][3] = As[(m + 8) * KPAD + kk + 4];
            }
            uint32_t bf[4][2];
            #pragma unroll
            for (int ni = 0; ni < 4; ni++) {
                int n = wn * 32 + ni * 8 + g;
                bf[ni][0] = Bs[n * KPAD + kk];
                bf[ni][1] = Bs[n * KPAD + kk + 4];
            }
            #pragma unroll
            for (int mi = 0; mi < 4; mi++)
                #pragma unroll
                for (int ni = 0; ni < 4; ni++)
                    mma_tf32(acc[mi][ni], af[mi], bf[ni]);
        }
        if (more) {
            const int so = ((c + 1) & 1) * 2 * STAGE_WORDS;
            #pragma unroll
            for (int i = 0; i < 4; i++) {
                uint32_t* pa = sm + so + (row + i * 32) * KPAD + kq4;
                uint32_t* pb = pa + STAGE_WORDS;
                uint4 ua = { f2tf32(ra[i].x), f2tf32(ra[i].y), f2tf32(ra[i].z), f2tf32(ra[i].w) };
                uint4 ub = { f2tf32(rb[i].x), f2tf32(rb[i].y), f2tf32(rb[i].z), f2tf32(rb[i].w) };
                *(uint4*)pa = ua;
                *(uint4*)pb = ub;
            }
        }
        __syncthreads();
    }

    // -------- epilogue --------
    #pragma unroll
    for (int mi = 0; mi < 4; mi++) {
        #pragma unroll
        for (int ni = 0; ni < 4; ni++) {
            const float* d = acc[mi][ni];
            int m = m0 + wm * 64 + mi * 16 + g;
            int n = n0 + wn * 32 + ni * 8 + t * 2;
            if (!trans) {
                float b0 = bias ? bias[n]     : 0.f;
                float b1 = bias ? bias[n + 1] : 0.f;
                float2 v0 = { d[0] * alpha + b0, d[1] * alpha + b1 };
                float2 v1 = { d[2] * alpha + b0, d[3] * alpha + b1 };
                *(float2*)(C + (size_t)m * ldc + n)       = v0;
                *(float2*)(C + (size_t)(m + 8) * ldc + n) = v1;
            } else {
                float b0 = bias ? bias[n]     : 0.f;
                float b1 = bias ? bias[n + 1] : 0.f;
                size_t o00 = (size_t)n * ldc + m;
                size_t o10 = (size_t)(n + 1) * ldc + m;
                float v0 = d[0] * alpha + b0;
                float v1 = d[1] * alpha + b1;
                float v2 = d[2] * alpha + b0;
                float v3 = d[3] * alpha + b1;
                if (resid) {
                    v0 += resid[o00]; v1 += resid[o10];
                    v2 += resid[o00 + 8]; v3 += resid[o10 + 8];
                }
                C[o00] = v0; C[o10] = v1; C[o00 + 8] = v2; C[o10 + 8] = v3;
            }
        }
    }
}

// ---------------- reductions ----------------
__device__ __forceinline__ float block_sum(float v) {
    __shared__ float smr[32];
    int w = threadIdx.x >> 5, l = threadIdx.x & 31;
    #pragma unroll
    for (int o = 16; o; o >>= 1) v += __shfl_xor_sync(0xffffffffu, v, o);
    __syncthreads();
    if (l == 0) smr[w] = v;
    __syncthreads();
    if (w == 0) {
        v = (l < (int)(blockDim.x >> 5)) ? smr[l] : 0.f;
        #pragma unroll
        for (int o = 16; o; o >>= 1) v += __shfl_xor_sync(0xffffffffu, v, o);
        if (l == 0) smr[0] = v;
    }
    __syncthreads();
    return smr[0];
}
__device__ __forceinline__ float block_max(float v) {
    __shared__ float smr[32];
    int w = threadIdx.x >> 5, l = threadIdx.x & 31;
    #pragma unroll
    for (int o = 16; o; o >>= 1) v = fmaxf(v, __shfl_xor_sync(0xffffffffu, v, o));
    __syncthreads();
    if (l == 0) smr[w] = v;
    __syncthreads();
    if (w == 0) {
        v = (l < (int)(blockDim.x >> 5)) ? smr[l] : -INFINITY;
        #pragma unroll
        for (int o = 16; o; o >>= 1) v = fmaxf(v, __shfl_xor_sync(0xffffffffu, v, o));
        if (l == 0) smr[0] = v;
    }
    __syncthreads();
    return smr[0];
}

// ---------------- GroupNorm stats ----------------
__global__ void __launch_bounds__(256)
gn_stats(const float* __restrict__ x) {
    int b = blockIdx.x >> 5, g = blockIdx.x & 31;
    const size_t base = ((size_t)b * C_DIM + (size_t)g * GCH) * NSP;
    const float4* xp = (const float4*)(x + base);
    const int NV = GCH * NSP / 4;
    float s = 0.f, s2 = 0.f;
    for (int i = threadIdx.x; i < NV; i += 256) {
        float4 v = xp[i];
        s  += v.x + v.y + v.z + v.w;
        s2 += v.x*v.x + v.y*v.y + v.z*v.z + v.w*v.w;
    }
    float ts = block_sum(s), ts2 = block_sum(s2);
    if (threadIdx.x == 0) {
        const float invn = 1.f / (GCH * NSP);
        float mean = ts * invn;
        float var = ts2 * invn - mean * mean;
        g_mean[blockIdx.x] = mean;
        g_inv[blockIdx.x]  = rsqrtf(var + 1e-6f);
    }
}

// ---------------- normalize + transpose: x[b][c][n] -> hnT[b][n][c] ----------------
__global__ void __launch_bounds__(256)
gn_norm_transpose(const float* __restrict__ x, const float* __restrict__ gamma,
                  const float* __restrict__ beta, float* __restrict__ hnT) {
    __shared__ float tile[32][33];
    int b = blockIdx.z;
    int n0 = blockIdx.x * 32, c0 = blockIdx.y * 32;
    int tx = threadIdx.x & 31, ty = threadIdx.x >> 5;   // 32 x 8
    const float* xb = x + (size_t)b * C_DIM * NSP;
    #pragma unroll
    for (int r = 0; r < 4; r++) {
        int c = c0 + ty + r * 8;
        int g = c >> 4;
        float mean = g_mean[b * NGROUPS + g], inv = g_inv[b * NGROUPS + g];
        float gm = gamma[c] * inv, bt = beta[c] - mean * gm;
        tile[ty + r * 8][tx] = xb[(size_t)c * NSP + n0 + tx] * gm + bt;
    }
    __syncthreads();
    float* hb = hnT + (size_t)b * NSP * C_DIM;
    #pragma unroll
    for (int r = 0; r < 4; r++) {
        int n = n0 + ty + r * 8;
        hb[(size_t)n * C_DIM + c0 + tx] = tile[tx][ty + r * 8];
    }
}

// ---------------- row softmax (in place, rows of 4096) ----------------
__global__ void __launch_bounds__(256)
softmax_kernel(float* __restrict__ sc) {
    float4* p = (float4*)(sc + (size_t)blockIdx.x * NSP);
    const int NV = NSP / 4;
    float mx = -INFINITY;
    for (int i = threadIdx.x; i < NV; i += 256) {
        float4 v = p[i];
        mx = fmaxf(mx, fmaxf(fmaxf(v.x, v.y), fmaxf(v.z, v.w)));
    }
    mx = block_max(mx);
    float s = 0.f;
    for (int i = threadIdx.x; i < NV; i += 256) {
        float4 v = p[i];
        v.x = __expf(v.x - mx); v.y = __expf(v.y - mx);
        v.z = __expf(v.z - mx); v.w = __expf(v.w - mx);
        s += v.x + v.y + v.z + v.w;
        p[i] = v;
    }
    s = block_sum(s);
    float r = 1.f / s;
    for (int i = threadIdx.x; i < NV; i += 256) {
        float4 v = p[i];
        v.x *= r; v.y *= r; v.z *= r; v.w *= r;
        p[i] = v;
    }
}

// ---------------- launch ----------------
extern "C" void kernel_launch(void* const* d_in, const int* in_sizes, int n_in,
                              void* d_out, int out_size) {
    const float* x     = (const float*)d_in[0];
    const float* gamma = (const float*)d_in[1];
    const float* beta  = (const float*)d_in[2];
    const float* wq = (const float*)d_in[3];  const float* bq = (const float*)d_in[4];
    const float* wk = (const float*)d_in[5];  const float* bk = (const float*)d_in[6];
    const float* wv = (const float*)d_in[7];  const float* bv = (const float*)d_in[8];
    const float* wo = (const float*)d_in[9];  const float* bo = (const float*)d_in[10];
    float* out = (float*)d_out;

    float *hnT, *q, *k, *v, *ao, *sc;
    cudaGetSymbolAddress((void**)&hnT, g_hnT);
    cudaGetSymbolAddress((void**)&q,   g_q);
    cudaGetSymbolAddress((void**)&k,   g_k);
    cudaGetSymbolAddress((void**)&v,   g_v);
    cudaGetSymbolAddress((void**)&ao,  g_ao);
    cudaGetSymbolAddress((void**)&sc,  g_sc);

    cudaFuncSetAttribute(mma_gemm, cudaFuncAttributeMaxDynamicSharedMemorySize, SMEM_DYN);

    const size_t BO = (size_t)C_DIM * NSP;
    const size_t SO = (size_t)NSP * NSP;
    const float scale = 0.044194173824159216f;   // 512^-0.5

    gn_stats<<<BATCH * NGROUPS, 256>>>(x);
    gn_norm_transpose<<<dim3(NSP/32, C_DIM/32, BATCH), 256>>>(x, gamma, beta, hnT);

    // QKV: D[token, cout] = hnT . W^T
    dim3 gqkv(C_DIM/NT, NSP/MT, BATCH);
    mma_gemm<<<gqkv, 256, SMEM_DYN>>>(hnT, BO, C_DIM, wq, 0, C_DIM,
                                      q, BO, C_DIM, C_DIM, 1.f, bq, nullptr, 0, 0);
    mma_gemm<<<gqkv, 256, SMEM_DYN>>>(hnT, BO, C_DIM, wk, 0, C_DIM,
                                      k, BO, C_DIM, C_DIM, 1.f, bk, nullptr, 0, 0);
    // V stored channel-major: trans store -> v[cout][token]
    mma_gemm<<<gqkv, 256, SMEM_DYN>>>(hnT, BO, C_DIM, wv, 0, C_DIM,
                                      v, BO, NSP, C_DIM, 1.f, bv, nullptr, 0, 1);

    // scores[i,j] = scale * q[i,:] . k[j,:]
    dim3 gsc(NSP/NT, NSP/MT, BATCH);
    mma_gemm<<<gsc, 256, SMEM_DYN>>>(q, BO, C_DIM, k, BO, C_DIM,
                                     sc, SO, NSP, C_DIM, scale, nullptr, nullptr, 0, 0);

    softmax_kernel<<<BATCH * NSP, 256>>>(sc);

    // ao[i, c] = attn[i,:] . v[c,:]
    dim3 gav(C_DIM/NT, NSP/MT, BATCH);
    mma_gemm<<<gav, 256, SMEM_DYN>>>(sc, SO, NSP, v, BO, NSP,
                                     ao, BO, C_DIM, NSP, 1.f, nullptr, nullptr, 0, 0);

    // out[cout][token] = ao . wo^T + bo + x
    mma_gemm<<<gav, 256, SMEM_DYN>>>(ao, BO, C_DIM, wo, 0, C_DIM,
                                     out, BO, NSP, C_DIM, 1.f, bo, x, BO, 1);
}

// round 5
// speedup vs baseline: 4.4372x; 1.1739x over previous
#include <cuda_runtime.h>
#include <cstdint>
#include <cstddef>

#define C_DIM 512
#define NSP   4096
#define BATCH 2
#define NGROUPS 32
#define GCH 16

#define MT 128
#define NT 128
#define KC 32
#define KPAD 36                      // 32 + 4 words padding (bank-safe, 16B-aligned)
#define STAGE_WORDS (MT * KPAD)      // 4608 words = 18KB per tile
#define NSTAGE 3
#define SMEM_DYN (NSTAGE * 2 * STAGE_WORDS * 4)   // 110592 B

// ---------------- scratch ----------------
__device__ float g_hnT[(size_t)BATCH*NSP*C_DIM];   // [b][token][cin]   (tf32-rounded)
__device__ float g_q  [(size_t)BATCH*NSP*C_DIM];   // [b][token][cout]  (tf32-rounded)
__device__ float g_k  [(size_t)BATCH*NSP*C_DIM];
__device__ float g_v  [(size_t)BATCH*C_DIM*NSP];   // [b][cout][token]  (tf32-rounded)
__device__ float g_ao [(size_t)BATCH*NSP*C_DIM];   // [b][token][c]     (tf32-rounded)
__device__ float g_sc [(size_t)BATCH*NSP*NSP];     // [b][i][j]
__device__ float g_wr [4 * C_DIM * C_DIM];         // rounded wq|wk|wv|wo
__device__ float g_mean[BATCH*NGROUPS];
__device__ float g_inv [BATCH*NGROUPS];

__device__ __forceinline__ uint32_t f2tf32(float x) {
    uint32_t r; asm("cvt.rna.tf32.f32 %0, %1;" : "=r"(r) : "f"(x)); return r;
}
__device__ __forceinline__ float rtf(float x) { return __uint_as_float(f2tf32(x)); }

__device__ __forceinline__ void cp16(uint32_t smem_dst, const void* gsrc) {
    asm volatile("cp.async.cg.shared.global [%0], [%1], 16;" :: "r"(smem_dst), "l"(gsrc));
}
#define CP_COMMIT() asm volatile("cp.async.commit_group;" ::: "memory")
#define CP_WAIT2()  asm volatile("cp.async.wait_group 2;" ::: "memory")

__device__ __forceinline__ void mma_tf32(float* d, const uint32_t* a, const uint32_t* b) {
    asm volatile(
        "mma.sync.aligned.m16n8k8.row.col.f32.tf32.tf32.f32 "
        "{%0,%1,%2,%3}, {%4,%5,%6,%7}, {%8,%9}, {%0,%1,%2,%3};"
        : "+f"(d[0]), "+f"(d[1]), "+f"(d[2]), "+f"(d[3])
        : "r"(a[0]), "r"(a[1]), "r"(a[2]), "r"(a[3]), "r"(b[0]), "r"(b[1]));
}

// ---------------- tf32 tensor-core GEMM, cp.async 3-stage ----------------
// D[m,n] = alpha * sum_k A[m,k]*B[n,k]   (A, B K-major, k contiguous, pre-tf32-rounded)
// trans==0: C[m*ldc+n] = D + bias[n]
// trans==1: C[n*ldc+m] = D + bias[n] + resid[n*ldc+m]
// rnd: round stored values to tf32
__global__ void __launch_bounds__(256, 2)
mma_gemm(const float* __restrict__ A, size_t aBat, int lda,
         const float* __restrict__ B, size_t bBat, int ldb,
         float* __restrict__ C, size_t cBat, int ldc,
         int K, float alpha,
         const float* __restrict__ bias,
         const float* __restrict__ resid, size_t rBat, int trans, int rnd) {
    extern __shared__ uint32_t sm[];

    const int tid  = threadIdx.x;
    const int wid  = tid >> 5, lane = tid & 31;
    const int wm   = wid & 1;         // m-half (64)
    const int wn   = wid >> 1;        // n-quarter (32)
    const int g    = lane >> 2;       // 0..7
    const int t    = lane & 3;        // 0..3

    const int m0 = blockIdx.y * MT, n0 = blockIdx.x * NT;
    const int z  = blockIdx.z;
    A += z * aBat + (size_t)m0 * lda;
    B += z * bBat + (size_t)n0 * ldb;
    C += z * cBat;
    if (resid) resid += z * rBat;

    const int row  = tid >> 3;         // 0..31 (+32 per i)
    const int col4 = (tid & 7) << 2;   // word offset within 32-k chunk

    uint32_t smbase;
    asm("{ .reg .u64 t; cvta.to.shared.u64 t, %1; cvt.u32.u64 %0, t; }"
        : "=r"(smbase) : "l"((void*)sm));

    const int nch = K / KC;
    float acc[4][4][4] = {};           // [mi][ni][reg]

    // ---- issue helper (inlined manually) ----
    #define ISSUE(cidx)  do {                                                     \
        const int _b  = (cidx) % NSTAGE;                                          \
        const int _kc = (cidx) * KC;                                              \
        uint32_t _sa = smbase + ((_b * 2 * STAGE_WORDS) + row * KPAD + col4) * 4; \
        uint32_t _sb = _sa + STAGE_WORDS * 4;                                     \
        _Pragma("unroll")                                                         \
        for (int _i = 0; _i < 4; _i++) {                                          \
            cp16(_sa + _i * 32 * KPAD * 4,                                        \
                 A + (size_t)(row + _i * 32) * lda + _kc + col4);                 \
            cp16(_sb + _i * 32 * KPAD * 4,                                        \
                 B + (size_t)(row + _i * 32) * ldb + _kc + col4);                 \
        }                                                                         \
    } while (0)

    ISSUE(0); CP_COMMIT();
    ISSUE(1); CP_COMMIT();

    for (int c = 0; c < nch; c++) {
        if (c + 2 < nch) { ISSUE(c + 2); }
        CP_COMMIT();
        CP_WAIT2();
        __syncthreads();

        const uint32_t* As = sm + (c % NSTAGE) * 2 * STAGE_WORDS;
        const uint32_t* Bs = As + STAGE_WORDS;
        #pragma unroll
        for (int ks = 0; ks < 4; ks++) {
            const int kk = ks * 8 + t;
            uint32_t af[4][4];
            #pragma unroll
            for (int mi = 0; mi < 4; mi++) {
                int m = wm * 64 + mi * 16 + g;
                af[mi][0] = As[m * KPAD + kk];
                af[mi][1] = As[(m + 8) * KPAD + kk];
                af[mi][2] = As[m * KPAD + kk + 4];
                af[mi][3] = As[(m + 8) * KPAD + kk + 4];
            }
            uint32_t bf[4][2];
            #pragma unroll
            for (int ni = 0; ni < 4; ni++) {
                int n = wn * 32 + ni * 8 + g;
                bf[ni][0] = Bs[n * KPAD + kk];
                bf[ni][1] = Bs[n * KPAD + kk + 4];
            }
            #pragma unroll
            for (int mi = 0; mi < 4; mi++)
                #pragma unroll
                for (int ni = 0; ni < 4; ni++)
                    mma_tf32(acc[mi][ni], af[mi], bf[ni]);
        }
        __syncthreads();
    }
    #undef ISSUE

    // -------- epilogue --------
    #pragma unroll
    for (int mi = 0; mi < 4; mi++) {
        #pragma unroll
        for (int ni = 0; ni < 4; ni++) {
            const float* d = acc[mi][ni];
            int m = m0 + wm * 64 + mi * 16 + g;
            int n = n0 + wn * 32 + ni * 8 + t * 2;
            float b0 = bias ? bias[n]     : 0.f;
            float b1 = bias ? bias[n + 1] : 0.f;
            if (!trans) {
                float2 v0 = { d[0] * alpha + b0, d[1] * alpha + b1 };
                float2 v1 = { d[2] * alpha + b0, d[3] * alpha + b1 };
                if (rnd) {
                    v0.x = rtf(v0.x); v0.y = rtf(v0.y);
                    v1.x = rtf(v1.x); v1.y = rtf(v1.y);
                }
                *(float2*)(C + (size_t)m * ldc + n)       = v0;
                *(float2*)(C + (size_t)(m + 8) * ldc + n) = v1;
            } else {
                size_t o00 = (size_t)n * ldc + m;
                size_t o10 = (size_t)(n + 1) * ldc + m;
                float v0 = d[0] * alpha + b0;
                float v1 = d[1] * alpha + b1;
                float v2 = d[2] * alpha + b0;
                float v3 = d[3] * alpha + b1;
                if (resid) {
                    v0 += resid[o00]; v1 += resid[o10];
                    v2 += resid[o00 + 8]; v3 += resid[o10 + 8];
                }
                if (rnd) { v0 = rtf(v0); v1 = rtf(v1); v2 = rtf(v2); v3 = rtf(v3); }
                C[o00] = v0; C[o10] = v1; C[o00 + 8] = v2; C[o10 + 8] = v3;
            }
        }
    }
}

// ---------------- reductions ----------------
__device__ __forceinline__ float block_sum(float v) {
    __shared__ float smr[32];
    int w = threadIdx.x >> 5, l = threadIdx.x & 31;
    #pragma unroll
    for (int o = 16; o; o >>= 1) v += __shfl_xor_sync(0xffffffffu, v, o);
    __syncthreads();
    if (l == 0) smr[w] = v;
    __syncthreads();
    if (w == 0) {
        v = (l < (int)(blockDim.x >> 5)) ? smr[l] : 0.f;
        #pragma unroll
        for (int o = 16; o; o >>= 1) v += __shfl_xor_sync(0xffffffffu, v, o);
        if (l == 0) smr[0] = v;
    }
    __syncthreads();
    return smr[0];
}
__device__ __forceinline__ float block_max(float v) {
    __shared__ float smr[32];
    int w = threadIdx.x >> 5, l = threadIdx.x & 31;
    #pragma unroll
    for (int o = 16; o; o >>= 1) v = fmaxf(v, __shfl_xor_sync(0xffffffffu, v, o));
    __syncthreads();
    if (l == 0) smr[w] = v;
    __syncthreads();
    if (w == 0) {
        v = (l < (int)(blockDim.x >> 5)) ? smr[l] : -INFINITY;
        #pragma unroll
        for (int o = 16; o; o >>= 1) v = fmaxf(v, __shfl_xor_sync(0xffffffffu, v, o));
        if (l == 0) smr[0] = v;
    }
    __syncthreads();
    return smr[0];
}

// ---------------- round weights to tf32 ----------------
__global__ void __launch_bounds__(256)
round_weights(const float* __restrict__ w0, const float* __restrict__ w1,
              const float* __restrict__ w2, const float* __restrict__ w3,
              float* __restrict__ o) {
    const int N = C_DIM * C_DIM;
    const float* src[4] = { w0, w1, w2, w3 };
    int which = blockIdx.y;
    const float4* s = (const float4*)src[which];
    float4* d = (float4*)(o + (size_t)which * N);
    for (int i = blockIdx.x * 256 + threadIdx.x; i < N / 4; i += gridDim.x * 256) {
        float4 v = s[i];
        v.x = rtf(v.x); v.y = rtf(v.y); v.z = rtf(v.z); v.w = rtf(v.w);
        d[i] = v;
    }
}

// ---------------- GroupNorm stats ----------------
__global__ void __launch_bounds__(256)
gn_stats(const float* __restrict__ x) {
    int b = blockIdx.x >> 5, g = blockIdx.x & 31;
    const size_t base = ((size_t)b * C_DIM + (size_t)g * GCH) * NSP;
    const float4* xp = (const float4*)(x + base);
    const int NV = GCH * NSP / 4;
    float s = 0.f, s2 = 0.f;
    for (int i = threadIdx.x; i < NV; i += 256) {
        float4 v = xp[i];
        s  += v.x + v.y + v.z + v.w;
        s2 += v.x*v.x + v.y*v.y + v.z*v.z + v.w*v.w;
    }
    float ts = block_sum(s), ts2 = block_sum(s2);
    if (threadIdx.x == 0) {
        const float invn = 1.f / (GCH * NSP);
        float mean = ts * invn;
        float var = ts2 * invn - mean * mean;
        g_mean[blockIdx.x] = mean;
        g_inv[blockIdx.x]  = rsqrtf(var + 1e-6f);
    }
}

// ---------------- normalize + transpose: x[b][c][n] -> hnT[b][n][c] (tf32) ----------------
__global__ void __launch_bounds__(256)
gn_norm_transpose(const float* __restrict__ x, const float* __restrict__ gamma,
                  const float* __restrict__ beta, float* __restrict__ hnT) {
    __shared__ float tile[32][33];
    int b = blockIdx.z;
    int n0 = blockIdx.x * 32, c0 = blockIdx.y * 32;
    int tx = threadIdx.x & 31, ty = threadIdx.x >> 5;   // 32 x 8
    const float* xb = x + (size_t)b * C_DIM * NSP;
    #pragma unroll
    for (int r = 0; r < 4; r++) {
        int c = c0 + ty + r * 8;
        int g = c >> 4;
        float mean = g_mean[b * NGROUPS + g], inv = g_inv[b * NGROUPS + g];
        float gm = gamma[c] * inv, bt = beta[c] - mean * gm;
        tile[ty + r * 8][tx] = rtf(xb[(size_t)c * NSP + n0 + tx] * gm + bt);
    }
    __syncthreads();
    float* hb = hnT + (size_t)b * NSP * C_DIM;
    #pragma unroll
    for (int r = 0; r < 4; r++) {
        int n = n0 + ty + r * 8;
        hb[(size_t)n * C_DIM + c0 + tx] = tile[tx][ty + r * 8];
    }
}

// ---------------- row softmax: one 16KB smem pass, tf32-rounded out ----------------
__global__ void __launch_bounds__(256)
softmax_kernel(float* __restrict__ sc) {
    __shared__ float rowbuf[NSP];
    float4* p  = (float4*)(sc + (size_t)blockIdx.x * NSP);
    float4* rb = (float4*)rowbuf;
    const int NV = NSP / 4;

    float mx = -INFINITY;
    for (int i = threadIdx.x; i < NV; i += 256) {
        float4 v = p[i];
        rb[i] = v;
        mx = fmaxf(mx, fmaxf(fmaxf(v.x, v.y), fmaxf(v.z, v.w)));
    }
    mx = block_max(mx);

    float s = 0.f;
    for (int i = threadIdx.x; i < NV; i += 256) {
        float4 v = rb[i];
        v.x = __expf(v.x - mx); v.y = __expf(v.y - mx);
        v.z = __expf(v.z - mx); v.w = __expf(v.w - mx);
        s += v.x + v.y + v.z + v.w;
        rb[i] = v;
    }
    s = block_sum(s);
    float r = 1.f / s;
    for (int i = threadIdx.x; i < NV; i += 256) {
        float4 v = rb[i];
        v.x = rtf(v.x * r); v.y = rtf(v.y * r);
        v.z = rtf(v.z * r); v.w = rtf(v.w * r);
        p[i] = v;
    }
}

// ---------------- launch ----------------
extern "C" void kernel_launch(void* const* d_in, const int* in_sizes, int n_in,
                              void* d_out, int out_size) {
    const float* x     = (const float*)d_in[0];
    const float* gamma = (const float*)d_in[1];
    const float* beta  = (const float*)d_in[2];
    const float* wq = (const float*)d_in[3];  const float* bq = (const float*)d_in[4];
    const float* wk = (const float*)d_in[5];  const float* bk = (const float*)d_in[6];
    const float* wv = (const float*)d_in[7];  const float* bv = (const float*)d_in[8];
    const float* wo = (const float*)d_in[9];  const float* bo = (const float*)d_in[10];
    float* out = (float*)d_out;

    float *hnT, *q, *k, *v, *ao, *sc, *wr;
    cudaGetSymbolAddress((void**)&hnT, g_hnT);
    cudaGetSymbolAddress((void**)&q,   g_q);
    cudaGetSymbolAddress((void**)&k,   g_k);
    cudaGetSymbolAddress((void**)&v,   g_v);
    cudaGetSymbolAddress((void**)&ao,  g_ao);
    cudaGetSymbolAddress((void**)&sc,  g_sc);
    cudaGetSymbolAddress((void**)&wr,  g_wr);

    cudaFuncSetAttribute(mma_gemm, cudaFuncAttributeMaxDynamicSharedMemorySize, SMEM_DYN);

    const size_t BO = (size_t)C_DIM * NSP;
    const size_t SO = (size_t)NSP * NSP;
    const size_t WO = (size_t)C_DIM * C_DIM;
    const float scale = 0.044194173824159216f;   // 512^-0.5
    const float* wq_r = wr;
    const float* wk_r = wr + WO;
    const float* wv_r = wr + 2 * WO;
    const float* wo_r = wr + 3 * WO;

    round_weights<<<dim3(64, 4), 256>>>(wq, wk, wv, wo, wr);
    gn_stats<<<BATCH * NGROUPS, 256>>>(x);
    gn_norm_transpose<<<dim3(NSP/32, C_DIM/32, BATCH), 256>>>(x, gamma, beta, hnT);

    // QKV: D[token, cout] = hnT . W^T
    dim3 gqkv(C_DIM/NT, NSP/MT, BATCH);
    mma_gemm<<<gqkv, 256, SMEM_DYN>>>(hnT, BO, C_DIM, wq_r, 0, C_DIM,
                                      q, BO, C_DIM, C_DIM, 1.f, bq, nullptr, 0, 0, 1);
    mma_gemm<<<gqkv, 256, SMEM_DYN>>>(hnT, BO, C_DIM, wk_r, 0, C_DIM,
                                      k, BO, C_DIM, C_DIM, 1.f, bk, nullptr, 0, 0, 1);
    // V stored channel-major: trans store -> v[cout][token]
    mma_gemm<<<gqkv, 256, SMEM_DYN>>>(hnT, BO, C_DIM, wv_r, 0, C_DIM,
                                      v, BO, NSP, C_DIM, 1.f, bv, nullptr, 0, 1, 1);

    // scores[i,j] = scale * q[i,:] . k[j,:]
    dim3 gsc(NSP/NT, NSP/MT, BATCH);
    mma_gemm<<<gsc, 256, SMEM_DYN>>>(q, BO, C_DIM, k, BO, C_DIM,
                                     sc, SO, NSP, C_DIM, scale, nullptr, nullptr, 0, 0, 0);

    softmax_kernel<<<BATCH * NSP, 256>>>(sc);

    // ao[i, c] = attn[i,:] . v[c,:]
    dim3 gav(C_DIM/NT, NSP/MT, BATCH);
    mma_gemm<<<gav, 256, SMEM_DYN>>>(sc, SO, NSP, v, BO, NSP,
                                     ao, BO, C_DIM, NSP, 1.f, nullptr, nullptr, 0, 0, 1);

    // out[cout][token] = ao . wo^T + bo + x
    mma_gemm<<<gav, 256, SMEM_DYN>>>(ao, BO, C_DIM, wo_r, 0, C_DIM,
                                     out, BO, NSP, C_DIM, 1.f, bo, x, BO, 1, 0);
}

// round 8
// speedup vs baseline: 7.6997x; 1.7353x over previous
#include <cuda_runtime.h>
#include <cuda_fp16.h>
#include <cstdint>
#include <cstddef>

#define C_DIM 512
#define NSP   4096
#define BATCH 2
#define NGROUPS 32
#define GCH 16

#define MT 128
#define NT 128
#define KC 64                         // halves per chunk
#define KPADW 36                      // words per row (32 data + 4 pad)
#define STAGE_WORDS (MT * KPADW)      // 4608 words = 18KB per tile
#define NSTAGE 3
#define SMEM_DYN (NSTAGE * 2 * STAGE_WORDS * 4)   // 110592 B

#define BO  ((size_t)C_DIM * NSP)     // 2097152 elems per batch (c-plane)
#define SO  ((size_t)NSP * NSP)       // 16777216 elems per batch
#define WO  ((size_t)C_DIM * C_DIM)

// ---------------- scratch ----------------
__device__ __half g_hnT[(size_t)BATCH * NSP * C_DIM];   // [b][token][cin]
__device__ __half g_q  [(size_t)BATCH * NSP * C_DIM];   // [b][token][cout]
__device__ __half g_k  [(size_t)BATCH * NSP * C_DIM];
__device__ __half g_v  [(size_t)BATCH * C_DIM * NSP];   // [b][cout][token]
__device__ __half g_ao [(size_t)BATCH * NSP * C_DIM];   // [b][token][c]
__device__ __half g_at [(size_t)BATCH * NSP * NSP];     // attn probs (half)
__device__ float  g_sc [(size_t)BATCH * NSP * NSP];     // raw scores (fp32)
__device__ __half g_wh [4 * C_DIM * C_DIM];             // wq|wk|wv|wo as half
__device__ float  g_bqkv[3 * C_DIM];                    // packed bias
__device__ float  g_mean[BATCH * NGROUPS];
__device__ float  g_inv [BATCH * NGROUPS];

__device__ __forceinline__ void cp16(uint32_t smem_dst, const void* gsrc) {
    asm volatile("cp.async.cg.shared.global [%0], [%1], 16;" :: "r"(smem_dst), "l"(gsrc));
}
#define CP_COMMIT() asm volatile("cp.async.commit_group;" ::: "memory")
#define CP_WAIT2()  asm volatile("cp.async.wait_group 2;" ::: "memory")

__device__ __forceinline__ void mma_f16(float* d, const uint32_t* a, const uint32_t* b) {
    asm volatile(
        "mma.sync.aligned.m16n8k16.row.col.f32.f16.f16.f32 "
        "{%0,%1,%2,%3}, {%4,%5,%6,%7}, {%8,%9}, {%0,%1,%2,%3};"
        : "+f"(d[0]), "+f"(d[1]), "+f"(d[2]), "+f"(d[3])
        : "r"(a[0]), "r"(a[1]), "r"(a[2]), "r"(a[3]), "r"(b[0]), "r"(b[1]));
}

// ---------------- fp16 tensor-core GEMM, cp.async 3-stage ----------------
// D[m,n] = alpha * sum_k A[m,k]*B[n,k]   (A, B half, K-major)
// mode 0: C0 float [m][4096] += bias? (scores)        (+z*SO)
// mode 1: C0 half  [m][512]  + bias   (AV out)        (+z*BO)
// mode 2: fused QKV: n<512 -> q half[m][512]; n<1024 -> k; else v half[c][4096] trans (+z*BO)
// mode 3: C0 float [n][4096] trans + bias[n] + resid  (proj)   (+z*BO)
__global__ void __launch_bounds__(256, 2)
hgemm(const __half* __restrict__ A, size_t aBat, int lda,
      const __half* __restrict__ B, size_t bBat, int ldb,
      int K, float alpha, const float* __restrict__ bias,
      void* C0, void* C1, void* C2,
      const float* __restrict__ resid, int mode) {
    extern __shared__ uint32_t sm[];

    const int tid  = threadIdx.x;
    const int wid  = tid >> 5, lane = tid & 31;
    const int wm   = wid & 1;          // m-half (64)
    const int wn   = wid >> 1;         // n-quarter (32)
    const int g    = lane >> 2;        // 0..7
    const int t    = lane & 3;         // 0..3

    const int m0 = blockIdx.y * MT, n0 = blockIdx.x * NT;
    const int z  = blockIdx.z;
    A += z * aBat + (size_t)m0 * lda;
    B += z * bBat + (size_t)n0 * ldb;

    const int row  = tid >> 3;          // 0..31 (+32 per i)
    const int colw = (tid & 7) << 2;    // word offset in row (0..28)
    const int colh = (tid & 7) << 3;    // half offset (0..56)

    uint32_t smbase;
    asm("{ .reg .u64 t; cvta.to.shared.u64 t, %1; cvt.u32.u64 %0, t; }"
        : "=r"(smbase) : "l"((void*)sm));

    const int nch = K / KC;
    float acc[4][4][4] = {};            // [mi][ni][reg]

    #define ISSUE(cidx)  do {                                                        \
        const int _b  = (cidx) % NSTAGE;                                             \
        const int _kc = (cidx) * KC;                                                 \
        uint32_t _sa = smbase + ((_b * 2 * STAGE_WORDS) + row * KPADW + colw) * 4;   \
        uint32_t _sb = _sa + STAGE_WORDS * 4;                                        \
        _Pragma("unroll")                                                            \
        for (int _i = 0; _i < 4; _i++) {                                             \
            cp16(_sa + _i * 32 * KPADW * 4,                                          \
                 A + (size_t)(row + _i * 32) * lda + _kc + colh);                    \
            cp16(_sb + _i * 32 * KPADW * 4,                                          \
                 B + (size_t)(row + _i * 32) * ldb + _kc + colh);                    \
        }                                                                            \
    } while (0)

    ISSUE(0); CP_COMMIT();
    ISSUE(1); CP_COMMIT();

    for (int c = 0; c < nch; c++) {
        if (c + 2 < nch) { ISSUE(c + 2); }
        CP_COMMIT();
        CP_WAIT2();
        __syncthreads();

        const uint32_t* As = sm + (c % NSTAGE) * 2 * STAGE_WORDS;
        const uint32_t* Bs = As + STAGE_WORDS;
        #pragma unroll
        for (int ks = 0; ks < 4; ks++) {
            const int kk = ks * 8 + t;
            uint32_t af[4][4];
            #pragma unroll
            for (int mi = 0; mi < 4; mi++) {
                int m = wm * 64 + mi * 16 + g;
                af[mi][0] = As[m * KPADW + kk];
                af[mi][1] = As[(m + 8) * KPADW + kk];
                af[mi][2] = As[m * KPADW + kk + 4];
                af[mi][3] = As[(m + 8) * KPADW + kk + 4];
            }
            uint32_t bf[4][2];
            #pragma unroll
            for (int ni = 0; ni < 4; ni++) {
                int n = wn * 32 + ni * 8 + g;
                bf[ni][0] = Bs[n * KPADW + kk];
                bf[ni][1] = Bs[n * KPADW + kk + 4];
            }
            #pragma unroll
            for (int mi = 0; mi < 4; mi++)
                #pragma unroll
                for (int ni = 0; ni < 4; ni++)
                    mma_f16(acc[mi][ni], af[mi], bf[ni]);
        }
        __syncthreads();
    }
    #undef ISSUE

    // -------- epilogue --------
    #pragma unroll
    for (int mi = 0; mi < 4; mi++) {
        #pragma unroll
        for (int ni = 0; ni < 4; ni++) {
            const float* d = acc[mi][ni];
            int m = m0 + wm * 64 + mi * 16 + g;
            int n = n0 + wn * 32 + ni * 8 + t * 2;
            float b0 = bias ? bias[n]     : 0.f;
            float b1 = bias ? bias[n + 1] : 0.f;
            float v0 = d[0] * alpha + b0;
            float v1 = d[1] * alpha + b1;
            float v2 = d[2] * alpha + b0;
            float v3 = d[3] * alpha + b1;
            if (mode == 0) {
                float* o = (float*)C0 + z * SO;
                *(float2*)(o + (size_t)m * NSP + n)       = make_float2(v0, v1);
                *(float2*)(o + (size_t)(m + 8) * NSP + n) = make_float2(v2, v3);
            } else if (mode == 1) {
                __half* o = (__half*)C0 + z * BO;
                *(__half2*)(o + (size_t)m * C_DIM + n)       = __floats2half2_rn(v0, v1);
                *(__half2*)(o + (size_t)(m + 8) * C_DIM + n) = __floats2half2_rn(v2, v3);
            } else if (mode == 2) {
                if (n < 1024) {
                    __half* o = (__half*)((n < 512) ? C0 : C1) + z * BO;
                    int nn = n & 511;
                    *(__half2*)(o + (size_t)m * C_DIM + nn)       = __floats2half2_rn(v0, v1);
                    *(__half2*)(o + (size_t)(m + 8) * C_DIM + nn) = __floats2half2_rn(v2, v3);
                } else {
                    __half* o = (__half*)C2 + z * BO;
                    int nn = n - 1024;
                    o[(size_t)nn * NSP + m]           = __float2half_rn(v0);
                    o[(size_t)(nn + 1) * NSP + m]     = __float2half_rn(v1);
                    o[(size_t)nn * NSP + m + 8]       = __float2half_rn(v2);
                    o[(size_t)(nn + 1) * NSP + m + 8] = __float2half_rn(v3);
                }
            } else {   // mode 3: trans float + residual
                float* o = (float*)C0 + z * BO;
                const float* r = resid + z * BO;
                size_t o0 = (size_t)n * NSP + m;
                size_t o1 = (size_t)(n + 1) * NSP + m;
                o[o0]     = v0 + r[o0];
                o[o1]     = v1 + r[o1];
                o[o0 + 8] = v2 + r[o0 + 8];
                o[o1 + 8] = v3 + r[o1 + 8];
            }
        }
    }
}

// ---------------- reductions ----------------
__device__ __forceinline__ float block_sum(float v) {
    __shared__ float smr[32];
    int w = threadIdx.x >> 5, l = threadIdx.x & 31;
    #pragma unroll
    for (int o = 16; o; o >>= 1) v += __shfl_xor_sync(0xffffffffu, v, o);
    __syncthreads();
    if (l == 0) smr[w] = v;
    __syncthreads();
    if (w == 0) {
        v = (l < (int)(blockDim.x >> 5)) ? smr[l] : 0.f;
        #pragma unroll
        for (int o = 16; o; o >>= 1) v += __shfl_xor_sync(0xffffffffu, v, o);
        if (l == 0) smr[0] = v;
    }
    __syncthreads();
    return smr[0];
}
__device__ __forceinline__ float block_max(float v) {
    __shared__ float smr[32];
    int w = threadIdx.x >> 5, l = threadIdx.x & 31;
    #pragma unroll
    for (int o = 16; o; o >>= 1) v = fmaxf(v, __shfl_xor_sync(0xffffffffu, v, o));
    __syncthreads();
    if (l == 0) smr[w] = v;
    __syncthreads();
    if (w == 0) {
        v = (l < (int)(blockDim.x >> 5)) ? smr[l] : -INFINITY;
        #pragma unroll
        for (int o = 16; o; o >>= 1) v = fmaxf(v, __shfl_xor_sync(0xffffffffu, v, o));
        if (l == 0) smr[0] = v;
    }
    __syncthreads();
    return smr[0];
}

// ---------------- weights -> half, biases -> packed ----------------
__global__ void __launch_bounds__(256)
round_weights(const float* __restrict__ w0, const float* __restrict__ w1,
              const float* __restrict__ w2, const float* __restrict__ w3,
              __half* __restrict__ o) {
    const int N = C_DIM * C_DIM;
    const float* src[4] = { w0, w1, w2, w3 };
    int which = blockIdx.y;
    const float4* s = (const float4*)src[which];
    __half2* d = (__half2*)(o + (size_t)which * N);
    for (int i = blockIdx.x * 256 + threadIdx.x; i < N / 4; i += gridDim.x * 256) {
        float4 v = s[i];
        d[i * 2]     = __floats2half2_rn(v.x, v.y);
        d[i * 2 + 1] = __floats2half2_rn(v.z, v.w);
    }
}
__global__ void __launch_bounds__(256)
pack_bias(const float* __restrict__ bq, const float* __restrict__ bk,
          const float* __restrict__ bv, float* __restrict__ o) {
    int i = blockIdx.x * 256 + threadIdx.x;
    if (i < C_DIM) o[i] = bq[i];
    else if (i < 2 * C_DIM) o[i] = bk[i - C_DIM];
    else if (i < 3 * C_DIM) o[i] = bv[i - 2 * C_DIM];
}

// ---------------- GroupNorm stats ----------------
__global__ void __launch_bounds__(256)
gn_stats(const float* __restrict__ x) {
    int b = blockIdx.x >> 5, g = blockIdx.x & 31;
    const size_t base = ((size_t)b * C_DIM + (size_t)g * GCH) * NSP;
    const float4* xp = (const float4*)(x + base);
    const int NV = GCH * NSP / 4;
    float s = 0.f, s2 = 0.f;
    for (int i = threadIdx.x; i < NV; i += 256) {
        float4 v = xp[i];
        s  += v.x + v.y + v.z + v.w;
        s2 += v.x*v.x + v.y*v.y + v.z*v.z + v.w*v.w;
    }
    float ts = block_sum(s), ts2 = block_sum(s2);
    if (threadIdx.x == 0) {
        const float invn = 1.f / (GCH * NSP);
        float mean = ts * invn;
        float var = ts2 * invn - mean * mean;
        g_mean[blockIdx.x] = mean;
        g_inv[blockIdx.x]  = rsqrtf(var + 1e-6f);
    }
}

// ---------------- normalize + transpose: x[b][c][n] -> hnT[b][n][c] (half) ----------------
__global__ void __launch_bounds__(256)
gn_norm_transpose(const float* __restrict__ x, const float* __restrict__ gamma,
                  const float* __restrict__ beta, __half* __restrict__ hnT) {
    __shared__ float tile[32][33];
    int b = blockIdx.z;
    int n0 = blockIdx.x * 32, c0 = blockIdx.y * 32;
    int tx = threadIdx.x & 31, ty = threadIdx.x >> 5;   // 32 x 8
    const float* xb = x + (size_t)b * C_DIM * NSP;
    #pragma unroll
    for (int r = 0; r < 4; r++) {
        int c = c0 + ty + r * 8;
        int g = c >> 4;
        float mean = g_mean[b * NGROUPS + g], inv = g_inv[b * NGROUPS + g];
        float gm = gamma[c] * inv, bt = beta[c] - mean * gm;
        tile[ty + r * 8][tx] = xb[(size_t)c * NSP + n0 + tx] * gm + bt;
    }
    __syncthreads();
    __half* hb = hnT + (size_t)b * NSP * C_DIM;
    #pragma unroll
    for (int r = 0; r < 4; r++) {
        int n = n0 + ty + r * 8;
        hb[(size_t)n * C_DIM + c0 + tx] = __float2half_rn(tile[tx][ty + r * 8]);
    }
}

// ---------------- row softmax: fp32 in, half out ----------------
__global__ void __launch_bounds__(256)
softmax_kernel(const float* __restrict__ sc, __half* __restrict__ at) {
    __shared__ float rowbuf[NSP];
    const float4* p = (const float4*)(sc + (size_t)blockIdx.x * NSP);
    __half2* o = (__half2*)(at + (size_t)blockIdx.x * NSP);
    float4* rb = (float4*)rowbuf;
    const int NV = NSP / 4;

    float mx = -INFINITY;
    for (int i = threadIdx.x; i < NV; i += 256) {
        float4 v = p[i];
        rb[i] = v;
        mx = fmaxf(mx, fmaxf(fmaxf(v.x, v.y), fmaxf(v.z, v.w)));
    }
    mx = block_max(mx);

    float s = 0.f;
    for (int i = threadIdx.x; i < NV; i += 256) {
        float4 v = rb[i];
        v.x = __expf(v.x - mx); v.y = __expf(v.y - mx);
        v.z = __expf(v.z - mx); v.w = __expf(v.w - mx);
        s += v.x + v.y + v.z + v.w;
        rb[i] = v;
    }
    s = block_sum(s);
    float r = 1.f / s;
    for (int i = threadIdx.x; i < NV; i += 256) {
        float4 v = rb[i];
        o[i * 2]     = __floats2half2_rn(v.x * r, v.y * r);
        o[i * 2 + 1] = __floats2half2_rn(v.z * r, v.w * r);
    }
}

// ---------------- launch ----------------
extern "C" void kernel_launch(void* const* d_in, const int* in_sizes, int n_in,
                              void* d_out, int out_size) {
    const float* x     = (const float*)d_in[0];
    const float* gamma = (const float*)d_in[1];
    const float* beta  = (const float*)d_in[2];
    const float* wq = (const float*)d_in[3];  const float* bq = (const float*)d_in[4];
    const float* wk = (const float*)d_in[5];  const float* bk = (const float*)d_in[6];
    const float* wv = (const float*)d_in[7];  const float* bv = (const float*)d_in[8];
    const float* wo = (const float*)d_in[9];  const float* bo = (const float*)d_in[10];
    float* out = (float*)d_out;

    __half *hnT, *q, *k, *v, *ao, *at, *wh;
    float *sc, *bqkv;
    cudaGetSymbolAddress((void**)&hnT, g_hnT);
    cudaGetSymbolAddress((void**)&q,   g_q);
    cudaGetSymbolAddress((void**)&k,   g_k);
    cudaGetSymbolAddress((void**)&v,   g_v);
    cudaGetSymbolAddress((void**)&ao,  g_ao);
    cudaGetSymbolAddress((void**)&at,  g_at);
    cudaGetSymbolAddress((void**)&sc,  g_sc);
    cudaGetSymbolAddress((void**)&wh,  g_wh);
    cudaGetSymbolAddress((void**)&bqkv, g_bqkv);

    cudaFuncSetAttribute(hgemm, cudaFuncAttributeMaxDynamicSharedMemorySize, SMEM_DYN);

    const float scale = 0.044194173824159216f;   // 512^-0.5

    round_weights<<<dim3(64, 4), 256>>>(wq, wk, wv, wo, wh);
    pack_bias<<<6, 256>>>(bq, bk, bv, bqkv);
    gn_stats<<<BATCH * NGROUPS, 256>>>(x);
    gn_norm_transpose<<<dim3(NSP/32, C_DIM/32, BATCH), 256>>>(x, gamma, beta, hnT);

    // fused QKV: M=4096 tokens x N=1536 (q|k|v) x K=512
    dim3 gqkv(1536 / NT, NSP / MT, BATCH);
    hgemm<<<gqkv, 256, SMEM_DYN>>>(hnT, BO, C_DIM, wh, 0, C_DIM,
                                   512, 1.f, bqkv, q, k, v, nullptr, 2);

    // scores[i,j] = scale * q[i,:] . k[j,:]  -> fp32
    dim3 gsc(NSP / NT, NSP / MT, BATCH);
    hgemm<<<gsc, 256, SMEM_DYN>>>(q, BO, C_DIM, k, BO, C_DIM,
                                  512, scale, nullptr, sc, nullptr, nullptr, nullptr, 0);

    softmax_kernel<<<BATCH * NSP, 256>>>(sc, at);

    // ao[i,c] = attn[i,:] . v[c,:]  (K = 4096)
    dim3 gav(C_DIM / NT, NSP / MT, BATCH);
    hgemm<<<gav, 256, SMEM_DYN>>>(at, SO, NSP, v, BO, NSP,
                                  NSP, 1.f, nullptr, ao, nullptr, nullptr, nullptr, 1);

    // out[c][token] = ao . wo^T + bo + x
    hgemm<<<gav, 256, SMEM_DYN>>>(ao, BO, C_DIM, wh + 3 * WO, 0, C_DIM,
                                  512, 1.f, bo, out, nullptr, nullptr, x, 3);
}

// round 9
// speedup vs baseline: 9.0977x; 1.1816x over previous
#include <cuda_runtime.h>
#include <cuda_fp16.h>
#include <cstdint>
#include <cstddef>

#define C_DIM 512
#define NSP   4096
#define BATCH 2
#define NGROUPS 32
#define GCH 16

#define MT 128
#define NT 128
#define KC 64                         // halves per chunk
#define KPADW 36                      // words per row (32 data + 4 pad)
#define STAGE_WORDS (MT * KPADW)      // 4608 words = 18KB per tile
#define NSTAGE 3
#define SMEM_DYN (NSTAGE * 2 * STAGE_WORDS * 4)   // 110592 B

#define BO  ((size_t)C_DIM * NSP)
#define SO  ((size_t)NSP * NSP)
#define WO  ((size_t)C_DIM * C_DIM)

// ---------------- scratch ----------------
__device__ __half g_hnT[(size_t)BATCH * NSP * C_DIM];   // [b][token][cin]
__device__ __half g_q  [(size_t)BATCH * NSP * C_DIM];   // [b][token][cout]
__device__ __half g_k  [(size_t)BATCH * NSP * C_DIM];
__device__ __half g_v  [(size_t)BATCH * C_DIM * NSP];   // [b][cout][token]
__device__ __half g_ao [(size_t)BATCH * NSP * C_DIM];   // [b][token][c]
__device__ __half g_at [(size_t)BATCH * NSP * NSP];     // exp(scores), unnormalized, half
__device__ float  g_rsum[BATCH * NSP];                  // softmax row sums
__device__ __half g_wh [4 * C_DIM * C_DIM];             // wq|wk|wv|wo as half
__device__ float  g_bqkv[3 * C_DIM];
__device__ float  g_mean[BATCH * NGROUPS];
__device__ float  g_inv [BATCH * NGROUPS];

__device__ __forceinline__ void cp16(uint32_t smem_dst, const void* gsrc) {
    asm volatile("cp.async.cg.shared.global [%0], [%1], 16;" :: "r"(smem_dst), "l"(gsrc));
}
#define CP_COMMIT() asm volatile("cp.async.commit_group;" ::: "memory")
#define CP_WAIT2()  asm volatile("cp.async.wait_group 2;" ::: "memory")

__device__ __forceinline__ void mma_f16(float* d, const uint32_t* a, const uint32_t* b) {
    asm volatile(
        "mma.sync.aligned.m16n8k16.row.col.f32.f16.f16.f32 "
        "{%0,%1,%2,%3}, {%4,%5,%6,%7}, {%8,%9}, {%0,%1,%2,%3};"
        : "+f"(d[0]), "+f"(d[1]), "+f"(d[2]), "+f"(d[3])
        : "r"(a[0]), "r"(a[1]), "r"(a[2]), "r"(a[3]), "r"(b[0]), "r"(b[1]));
}
__device__ __forceinline__ void ldsm_x4(uint32_t& r0, uint32_t& r1, uint32_t& r2,
                                        uint32_t& r3, uint32_t addr) {
    asm volatile("ldmatrix.sync.aligned.m8n8.x4.shared.b16 {%0,%1,%2,%3}, [%4];"
                 : "=r"(r0), "=r"(r1), "=r"(r2), "=r"(r3) : "r"(addr));
}

// ---------------- fp16 tensor-core GEMM, cp.async 3-stage, ldmatrix ----------------
// D[m,n] = alpha * sum_k A[m,k]*B[n,k]   (A, B half, K-major)
// mode 0: at half [m][4096] = exp(D); atomicAdd row sums into rsum   (+z*SO / +z*NSP)
// mode 1: C0 half [m][512] = D / rsum[m]                             (+z*BO)
// mode 2: fused QKV: n<512 -> q; n<1024 -> k; else v half[c][4096] trans
// mode 3: C0 float [n][4096] trans + bias[n] + resid
__global__ void __launch_bounds__(256, 2)
hgemm(const __half* __restrict__ A, size_t aBat, int lda,
      const __half* __restrict__ B, size_t bBat, int ldb,
      int K, float alpha, const float* __restrict__ bias,
      void* C0, void* C1, void* C2,
      const float* __restrict__ resid, float* __restrict__ rsum, int mode) {
    extern __shared__ uint32_t sm[];

    const int tid  = threadIdx.x;
    const int wid  = tid >> 5, lane = tid & 31;
    const int wm   = wid & 1;          // m-half (64)
    const int wn   = wid >> 1;         // n-quarter (32)
    const int g    = lane >> 2;        // 0..7
    const int t    = lane & 3;         // 0..3

    const int m0 = blockIdx.y * MT, n0 = blockIdx.x * NT;
    const int z  = blockIdx.z;
    A += z * aBat + (size_t)m0 * lda;
    B += z * bBat + (size_t)n0 * ldb;

    const int row  = tid >> 3;          // 0..31 (+32 per i)
    const int colw = (tid & 7) << 2;
    const int colh = (tid & 7) << 3;

    uint32_t smbase;
    asm("{ .reg .u64 t; cvta.to.shared.u64 t, %1; cvt.u32.u64 %0, t; }"
        : "=r"(smbase) : "l"((void*)sm));

    // ldmatrix per-lane base byte offsets (within a stage tile)
    const uint32_t aoff = (((uint32_t)(wm * 64 + (lane & 15)) * KPADW) + ((lane >> 4) << 2)) * 4;
    const uint32_t boff = (((uint32_t)(wn * 32 + (lane & 7) + ((lane >> 4) << 3)) * KPADW)
                           + (((lane >> 3) & 1) << 2)) * 4;

    const int nch = K / KC;
    float acc[4][4][4] = {};            // [mi][ni][reg]

    #define ISSUE(cidx)  do {                                                        \
        const int _b  = (cidx) % NSTAGE;                                             \
        const int _kc = (cidx) * KC;                                                 \
        uint32_t _sa = smbase + ((_b * 2 * STAGE_WORDS) + row * KPADW + colw) * 4;   \
        uint32_t _sb = _sa + STAGE_WORDS * 4;                                        \
        _Pragma("unroll")                                                            \
        for (int _i = 0; _i < 4; _i++) {                                             \
            cp16(_sa + _i * 32 * KPADW * 4,                                          \
                 A + (size_t)(row + _i * 32) * lda + _kc + colh);                    \
            cp16(_sb + _i * 32 * KPADW * 4,                                          \
                 B + (size_t)(row + _i * 32) * ldb + _kc + colh);                    \
        }                                                                            \
    } while (0)

    ISSUE(0); CP_COMMIT();
    ISSUE(1); CP_COMMIT();

    for (int c = 0; c < nch; c++) {
        if (c + 2 < nch) { ISSUE(c + 2); }
        CP_COMMIT();
        CP_WAIT2();
        __syncthreads();

        const uint32_t sA = smbase + (c % NSTAGE) * 2 * STAGE_WORDS * 4;
        const uint32_t sB = sA + STAGE_WORDS * 4;
        #pragma unroll
        for (int ks = 0; ks < 4; ks++) {
            uint32_t af[4][4], bf[4][2];
            #pragma unroll
            for (int mi = 0; mi < 4; mi++)
                ldsm_x4(af[mi][0], af[mi][1], af[mi][2], af[mi][3],
                        sA + aoff + mi * (16 * KPADW * 4) + ks * 32);
            #pragma unroll
            for (int nj = 0; nj < 2; nj++)
                ldsm_x4(bf[2 * nj][0], bf[2 * nj][1], bf[2 * nj + 1][0], bf[2 * nj + 1][1],
                        sB + boff + nj * (16 * KPADW * 4) + ks * 32);
            #pragma unroll
            for (int mi = 0; mi < 4; mi++)
                #pragma unroll
                for (int ni = 0; ni < 4; ni++)
                    mma_f16(acc[mi][ni], af[mi], bf[ni]);
        }
        __syncthreads();
    }
    #undef ISSUE

    // -------- epilogue --------
    #pragma unroll
    for (int mi = 0; mi < 4; mi++) {
        int m = m0 + wm * 64 + mi * 16 + g;
        float rs0 = 0.f, rs1 = 0.f;          // mode 0: row-sum partials
        float ri0 = 1.f, ri1 = 1.f;          // mode 1: reciprocal row sums
        if (mode == 1) {
            ri0 = __frcp_rn(rsum[z * NSP + m]);
            ri1 = __frcp_rn(rsum[z * NSP + m + 8]);
        }
        #pragma unroll
        for (int ni = 0; ni < 4; ni++) {
            const float* d = acc[mi][ni];
            int n = n0 + wn * 32 + ni * 8 + t * 2;
            float b0 = bias ? bias[n]     : 0.f;
            float b1 = bias ? bias[n + 1] : 0.f;
            float v0 = d[0] * alpha + b0;
            float v1 = d[1] * alpha + b1;
            float v2 = d[2] * alpha + b0;
            float v3 = d[3] * alpha + b1;
            if (mode == 0) {
                v0 = __expf(v0); v1 = __expf(v1);
                v2 = __expf(v2); v3 = __expf(v3);
                rs0 += v0 + v1; rs1 += v2 + v3;
                __half* o = (__half*)C0 + z * SO;
                *(__half2*)(o + (size_t)m * NSP + n)       = __floats2half2_rn(v0, v1);
                *(__half2*)(o + (size_t)(m + 8) * NSP + n) = __floats2half2_rn(v2, v3);
            } else if (mode == 1) {
                __half* o = (__half*)C0 + z * BO;
                *(__half2*)(o + (size_t)m * C_DIM + n)       = __floats2half2_rn(v0 * ri0, v1 * ri0);
                *(__half2*)(o + (size_t)(m + 8) * C_DIM + n) = __floats2half2_rn(v2 * ri1, v3 * ri1);
            } else if (mode == 2) {
                if (n < 1024) {
                    __half* o = (__half*)((n < 512) ? C0 : C1) + z * BO;
                    int nn = n & 511;
                    *(__half2*)(o + (size_t)m * C_DIM + nn)       = __floats2half2_rn(v0, v1);
                    *(__half2*)(o + (size_t)(m + 8) * C_DIM + nn) = __floats2half2_rn(v2, v3);
                } else {
                    __half* o = (__half*)C2 + z * BO;
                    int nn = n - 1024;
                    o[(size_t)nn * NSP + m]           = __float2half_rn(v0);
                    o[(size_t)(nn + 1) * NSP + m]     = __float2half_rn(v1);
                    o[(size_t)nn * NSP + m + 8]       = __float2half_rn(v2);
                    o[(size_t)(nn + 1) * NSP + m + 8] = __float2half_rn(v3);
                }
            } else {   // mode 3: trans float + residual
                float* o = (float*)C0 + z * BO;
                const float* r = resid + z * BO;
                size_t o0 = (size_t)n * NSP + m;
                size_t o1 = (size_t)(n + 1) * NSP + m;
                o[o0]     = v0 + r[o0];
                o[o1]     = v1 + r[o1];
                o[o0 + 8] = v2 + r[o0 + 8];
                o[o1 + 8] = v3 + r[o1 + 8];
            }
        }
        if (mode == 0) {
            // reduce across the 4 lanes sharing each row (t = 0..3)
            rs0 += __shfl_xor_sync(0xffffffffu, rs0, 1);
            rs0 += __shfl_xor_sync(0xffffffffu, rs0, 2);
            rs1 += __shfl_xor_sync(0xffffffffu, rs1, 1);
            rs1 += __shfl_xor_sync(0xffffffffu, rs1, 2);
            if (t == 0) {
                atomicAdd(&rsum[z * NSP + m], rs0);
                atomicAdd(&rsum[z * NSP + m + 8], rs1);
            }
        }
    }
}

// ---------------- zero row sums ----------------
__global__ void __launch_bounds__(1024)
zero_rsum(float* __restrict__ r) {
    r[blockIdx.x * 1024 + threadIdx.x] = 0.f;
}

// ---------------- reductions ----------------
__device__ __forceinline__ float block_sum(float v) {
    __shared__ float smr[32];
    int w = threadIdx.x >> 5, l = threadIdx.x & 31;
    #pragma unroll
    for (int o = 16; o; o >>= 1) v += __shfl_xor_sync(0xffffffffu, v, o);
    __syncthreads();
    if (l == 0) smr[w] = v;
    __syncthreads();
    if (w == 0) {
        v = (l < (int)(blockDim.x >> 5)) ? smr[l] : 0.f;
        #pragma unroll
        for (int o = 16; o; o >>= 1) v += __shfl_xor_sync(0xffffffffu, v, o);
        if (l == 0) smr[0] = v;
    }
    __syncthreads();
    return smr[0];
}

// ---------------- weights -> half, biases -> packed ----------------
__global__ void __launch_bounds__(256)
round_weights(const float* __restrict__ w0, const float* __restrict__ w1,
              const float* __restrict__ w2, const float* __restrict__ w3,
              __half* __restrict__ o) {
    const int N = C_DIM * C_DIM;
    const float* src[4] = { w0, w1, w2, w3 };
    int which = blockIdx.y;
    const float4* s = (const float4*)src[which];
    __half2* d = (__half2*)(o + (size_t)which * N);
    for (int i = blockIdx.x * 256 + threadIdx.x; i < N / 4; i += gridDim.x * 256) {
        float4 v = s[i];
        d[i * 2]     = __floats2half2_rn(v.x, v.y);
        d[i * 2 + 1] = __floats2half2_rn(v.z, v.w);
    }
}
__global__ void __launch_bounds__(256)
pack_bias(const float* __restrict__ bq, const float* __restrict__ bk,
          const float* __restrict__ bv, float* __restrict__ o) {
    int i = blockIdx.x * 256 + threadIdx.x;
    if (i < C_DIM) o[i] = bq[i];
    else if (i < 2 * C_DIM) o[i] = bk[i - C_DIM];
    else if (i < 3 * C_DIM) o[i] = bv[i - 2 * C_DIM];
}

// ---------------- GroupNorm stats ----------------
__global__ void __launch_bounds__(256)
gn_stats(const float* __restrict__ x) {
    int b = blockIdx.x >> 5, g = blockIdx.x & 31;
    const size_t base = ((size_t)b * C_DIM + (size_t)g * GCH) * NSP;
    const float4* xp = (const float4*)(x + base);
    const int NV = GCH * NSP / 4;
    float s = 0.f, s2 = 0.f;
    for (int i = threadIdx.x; i < NV; i += 256) {
        float4 v = xp[i];
        s  += v.x + v.y + v.z + v.w;
        s2 += v.x*v.x + v.y*v.y + v.z*v.z + v.w*v.w;
    }
    float ts = block_sum(s), ts2 = block_sum(s2);
    if (threadIdx.x == 0) {
        const float invn = 1.f / (GCH * NSP);
        float mean = ts * invn;
        float var = ts2 * invn - mean * mean;
        g_mean[blockIdx.x] = mean;
        g_inv[blockIdx.x]  = rsqrtf(var + 1e-6f);
    }
}

// ---------------- normalize + transpose: x[b][c][n] -> hnT[b][n][c] (half) ----------------
__global__ void __launch_bounds__(256)
gn_norm_transpose(const float* __restrict__ x, const float* __restrict__ gamma,
                  const float* __restrict__ beta, __half* __restrict__ hnT) {
    __shared__ float tile[32][33];
    int b = blockIdx.z;
    int n0 = blockIdx.x * 32, c0 = blockIdx.y * 32;
    int tx = threadIdx.x & 31, ty = threadIdx.x >> 5;   // 32 x 8
    const float* xb = x + (size_t)b * C_DIM * NSP;
    #pragma unroll
    for (int r = 0; r < 4; r++) {
        int c = c0 + ty + r * 8;
        int g = c >> 4;
        float mean = g_mean[b * NGROUPS + g], inv = g_inv[b * NGROUPS + g];
        float gm = gamma[c] * inv, bt = beta[c] - mean * gm;
        tile[ty + r * 8][tx] = xb[(size_t)c * NSP + n0 + tx] * gm + bt;
    }
    __syncthreads();
    __half* hb = hnT + (size_t)b * NSP * C_DIM;
    #pragma unroll
    for (int r = 0; r < 4; r++) {
        int n = n0 + ty + r * 8;
        hb[(size_t)n * C_DIM + c0 + tx] = __float2half_rn(tile[tx][ty + r * 8]);
    }
}

// ---------------- launch ----------------
extern "C" void kernel_launch(void* const* d_in, const int* in_sizes, int n_in,
                              void* d_out, int out_size) {
    const float* x     = (const float*)d_in[0];
    const float* gamma = (const float*)d_in[1];
    const float* beta  = (const float*)d_in[2];
    const float* wq = (const float*)d_in[3];  const float* bq = (const float*)d_in[4];
    const float* wk = (const float*)d_in[5];  const float* bk = (const float*)d_in[6];
    const float* wv = (const float*)d_in[7];  const float* bv = (const float*)d_in[8];
    const float* wo = (const float*)d_in[9];  const float* bo = (const float*)d_in[10];
    float* out = (float*)d_out;

    __half *hnT, *q, *k, *v, *ao, *at, *wh;
    float *rsum, *bqkv;
    cudaGetSymbolAddress((void**)&hnT, g_hnT);
    cudaGetSymbolAddress((void**)&q,   g_q);
    cudaGetSymbolAddress((void**)&k,   g_k);
    cudaGetSymbolAddress((void**)&v,   g_v);
    cudaGetSymbolAddress((void**)&ao,  g_ao);
    cudaGetSymbolAddress((void**)&at,  g_at);
    cudaGetSymbolAddress((void**)&rsum, g_rsum);
    cudaGetSymbolAddress((void**)&wh,  g_wh);
    cudaGetSymbolAddress((void**)&bqkv, g_bqkv);

    cudaFuncSetAttribute(hgemm, cudaFuncAttributeMaxDynamicSharedMemorySize, SMEM_DYN);

    const float scale = 0.044194173824159216f;   // 512^-0.5

    round_weights<<<dim3(64, 4), 256>>>(wq, wk, wv, wo, wh);
    pack_bias<<<6, 256>>>(bq, bk, bv, bqkv);
    zero_rsum<<<BATCH * NSP / 1024, 1024>>>(rsum);
    gn_stats<<<BATCH * NGROUPS, 256>>>(x);
    gn_norm_transpose<<<dim3(NSP/32, C_DIM/32, BATCH), 256>>>(x, gamma, beta, hnT);

    // fused QKV: M=4096 tokens x N=1536 (q|k|v) x K=512
    dim3 gqkv(1536 / NT, NSP / MT, BATCH);
    hgemm<<<gqkv, 256, SMEM_DYN>>>(hnT, BO, C_DIM, wh, 0, C_DIM,
                                   512, 1.f, bqkv, q, k, v, nullptr, nullptr, 2);

    // exp-scores + row sums: at[i][j] = exp(scale * q.k), rsum[i] += ...
    dim3 gsc(NSP / NT, NSP / MT, BATCH);
    hgemm<<<gsc, 256, SMEM_DYN>>>(q, BO, C_DIM, k, BO, C_DIM,
                                  512, scale, nullptr, at, nullptr, nullptr, nullptr, rsum, 0);

    // ao[i,c] = (at[i,:] . v[c,:]) / rsum[i]   (K = 4096)
    dim3 gav(C_DIM / NT, NSP / MT, BATCH);
    hgemm<<<gav, 256, SMEM_DYN>>>(at, SO, NSP, v, BO, NSP,
                                  NSP, 1.f, nullptr, ao, nullptr, nullptr, nullptr, rsum, 1);

    // out[c][token] = ao . wo^T + bo + x
    hgemm<<<gav, 256, SMEM_DYN>>>(ao, BO, C_DIM, wh + 3 * WO, 0, C_DIM,
                                  512, 1.f, bo, out, nullptr, nullptr, x, nullptr, 3);
}